// round 8
// baseline (speedup 1.0000x reference)
#include <cuda_runtime.h>
#include <math_constants.h>

#define N_BINS 15
#define RPW 8          // rows per warp per iter (2 rows per lane, 4 segments)

// Global scratch (no allocation allowed). Zeroed at module load; the fused
// finalizer re-zeroes after each use, so every graph replay starts from zero.
__device__ float    g_cnt[N_BINS];
__device__ float    g_conf[N_BINS];
__device__ float    g_acc[N_BINS];
__device__ unsigned g_done;

__device__ __forceinline__ float ex2f(float x) {
    float r;
    asm volatile("ex2.approx.f32 %0, %1;" : "=f"(r) : "f"(x));
    return r;
}

#define LOG2E 1.4426950408889634f

// One row-group = 8 consecutive rows (4 KB). 8 lanes per row, 2 rows per lane:
// each LDG.128 covers 4 FULL 128B lines. Loads for group k+1 are issued before
// group k's compute (2-stage register pipeline) so every warp keeps ~4KB
// outstanding continuously.
struct RowGroup {
    float4 vA[4], vB[4];
    float  lvA, lvB;     // label-column logits (dependent loads)
};

__device__ __forceinline__ void load_group(
    RowGroup& g, const float4* __restrict__ logits4,
    const float* __restrict__ logits, const int* __restrict__ labels,
    int base, int seg, int sub, int nrows)
{
    int rowA = base + seg;
    int rowB = base + seg + 4;
    int rowAc = (rowA < nrows) ? rowA : (nrows - 1);
    int rowBc = (rowB < nrows) ? rowB : (nrows - 1);

    const float4* rpA = logits4 + (size_t)rowAc * 32 + sub;
    const float4* rpB = logits4 + (size_t)rowBc * 32 + sub;
    #pragma unroll
    for (int i = 0; i < 4; i++) g.vA[i] = rpA[8 * i];
    #pragma unroll
    for (int i = 0; i < 4; i++) g.vB[i] = rpB[8 * i];

    int labA = labels[rowAc];
    int labB = labels[rowBc];
    g.lvA = logits[(size_t)rowAc * 128 + labA];
    g.lvB = logits[(size_t)rowBc * 128 + labB];
}

__device__ __forceinline__ void compute_group(
    const RowGroup& g, int base, int nrows, int lane,
    float& r_cnt, float& r_conf, float& r_acc)
{
    // ---- per-lane max over 16 values each row ----
    float p0 = fmaxf(fmaxf(g.vA[0].x, g.vA[0].y), fmaxf(g.vA[0].z, g.vA[0].w));
    float p1 = fmaxf(fmaxf(g.vA[1].x, g.vA[1].y), fmaxf(g.vA[1].z, g.vA[1].w));
    float p2 = fmaxf(fmaxf(g.vA[2].x, g.vA[2].y), fmaxf(g.vA[2].z, g.vA[2].w));
    float p3 = fmaxf(fmaxf(g.vA[3].x, g.vA[3].y), fmaxf(g.vA[3].z, g.vA[3].w));
    float mA = fmaxf(fmaxf(p0, p1), fmaxf(p2, p3));
    float q0 = fmaxf(fmaxf(g.vB[0].x, g.vB[0].y), fmaxf(g.vB[0].z, g.vB[0].w));
    float q1 = fmaxf(fmaxf(g.vB[1].x, g.vB[1].y), fmaxf(g.vB[1].z, g.vB[1].w));
    float q2 = fmaxf(fmaxf(g.vB[2].x, g.vB[2].y), fmaxf(g.vB[2].z, g.vB[2].w));
    float q3 = fmaxf(fmaxf(g.vB[3].x, g.vB[3].y), fmaxf(g.vB[3].z, g.vB[3].w));
    float mB = fmaxf(fmaxf(q0, q1), fmaxf(q2, q3));

    // 3-level segment butterflies (8-lane segments), two rows interleaved
    #pragma unroll
    for (int off = 1; off <= 4; off <<= 1) {
        mA = fmaxf(mA, __shfl_xor_sync(0xffffffffu, mA, off));
        mB = fmaxf(mB, __shfl_xor_sync(0xffffffffu, mB, off));
    }

    // ---- sum of exp(x - m) = ex2(x*log2e - m*log2e) ----
    float mLA = mA * LOG2E, mLB = mB * LOG2E;
    float sA = 0.0f, sB = 0.0f;
    #pragma unroll
    for (int i = 0; i < 4; i++) {
        float a0 = ex2f(fmaf(g.vA[i].x, LOG2E, -mLA));
        float a1 = ex2f(fmaf(g.vA[i].y, LOG2E, -mLA));
        float a2 = ex2f(fmaf(g.vA[i].z, LOG2E, -mLA));
        float a3 = ex2f(fmaf(g.vA[i].w, LOG2E, -mLA));
        sA += (a0 + a1) + (a2 + a3);
        float b0 = ex2f(fmaf(g.vB[i].x, LOG2E, -mLB));
        float b1 = ex2f(fmaf(g.vB[i].y, LOG2E, -mLB));
        float b2 = ex2f(fmaf(g.vB[i].z, LOG2E, -mLB));
        float b3 = ex2f(fmaf(g.vB[i].w, LOG2E, -mLB));
        sB += (b0 + b1) + (b2 + b3);
    }
    #pragma unroll
    for (int off = 1; off <= 4; off <<= 1) {
        sA += __shfl_xor_sync(0xffffffffu, sA, off);
        sB += __shfl_xor_sync(0xffffffffu, sB, off);
    }

    float confA = __fdividef(1.0f, sA);    // = exp(max)/sum exp
    float confB = __fdividef(1.0f, sB);

    // accuracy ballots: row r (0..3) -> bit 8r of bA; row 4+r -> bit 8r of bB
    unsigned bA = __ballot_sync(0xffffffffu, g.lvA == mA);
    unsigned bB = __ballot_sync(0xffffffffu, g.lvB == mB);

    int nr = min(RPW, nrows - base);
    #pragma unroll
    for (int r = 0; r < RPW; r++) {
        float cf = (r < 4)
                 ? __shfl_sync(0xffffffffu, confA, (r & 3) * 8)
                 : __shfl_sync(0xffffffffu, confB, (r & 3) * 8);
        unsigned abit = (r < 4) ? ((bA >> (8 * (r & 3))) & 1u)
                                : ((bB >> (8 * (r & 3))) & 1u);
        // bin i covers (i/15, (i+1)/15]
        int bin = min(__float2int_ru(cf * (float)N_BINS) - 1, N_BINS - 1);
        if (bin == lane && r < nr) {
            r_cnt  += 1.0f;
            r_conf += cf;
            r_acc  += (float)abit;
        }
    }
}

__global__ void __launch_bounds__(256) mce_main_kernel(
    const float4* __restrict__ logits4,   // [nrows * 32] float4
    const float*  __restrict__ logits,    // same buffer, scalar view
    const int*    __restrict__ labels,    // [nrows]
    float*        __restrict__ out,
    int nrows)
{
    __shared__ float s_cnt[N_BINS];
    __shared__ float s_conf[N_BINS];
    __shared__ float s_acc[N_BINS];
    __shared__ bool  s_last;

    int tid = threadIdx.x;
    if (tid < N_BINS) {
        s_cnt[tid]  = 0.0f;
        s_conf[tid] = 0.0f;
        s_acc[tid]  = 0.0f;
    }
    __syncthreads();

    int lane   = tid & 31;
    int seg    = lane >> 3;                // segment 0..3
    int sub    = lane & 7;                 // lane within 8-lane segment
    int warp   = (blockIdx.x * blockDim.x + tid) >> 5;
    int nwarps = (gridDim.x * blockDim.x) >> 5;
    int stride = nwarps * RPW;

    float r_cnt = 0.0f, r_conf = 0.0f, r_acc = 0.0f;

    // ---- 2-stage software pipeline over row groups ----
    RowGroup g0, g1;
    int base = warp * RPW;
    if (base < nrows) {
        load_group(g0, logits4, logits, labels, base, seg, sub, nrows);
        while (true) {
            int nb = base + stride;
            if (nb < nrows)
                load_group(g1, logits4, logits, labels, nb, seg, sub, nrows);
            compute_group(g0, base, nrows, lane, r_cnt, r_conf, r_acc);
            base = nb;
            if (base >= nrows) break;

            nb = base + stride;
            if (nb < nrows)
                load_group(g0, logits4, logits, labels, nb, seg, sub, nrows);
            compute_group(g1, base, nrows, lane, r_cnt, r_conf, r_acc);
            base = nb;
            if (base >= nrows) break;
        }
    }

    // ---- flush: registers -> shared -> global (once per block) ----
    if (lane < N_BINS && r_cnt != 0.0f) {
        atomicAdd(&s_cnt[lane],  r_cnt);
        atomicAdd(&s_conf[lane], r_conf);
        atomicAdd(&s_acc[lane],  r_acc);
    }
    __syncthreads();
    if (tid < N_BINS) {
        float c = s_cnt[tid];
        if (c != 0.0f) {
            atomicAdd(&g_cnt[tid],  c);
            atomicAdd(&g_conf[tid], s_conf[tid]);
            atomicAdd(&g_acc[tid],  s_acc[tid]);
        }
    }
    __threadfence();
    __syncthreads();

    // ---- last block finalizes (fused; no second launch) ----
    if (tid == 0)
        s_last = (atomicAdd(&g_done, 1u) == gridDim.x - 1u);
    __syncthreads();
    if (s_last && tid == 0) {
        volatile float* vc = g_cnt;
        volatile float* vp = g_conf;
        volatile float* va = g_acc;
        float mce = -CUDART_INF_F;
        #pragma unroll
        for (int i = 0; i < N_BINS; i++) {
            float c    = vc[i];
            float prob = 0.0f, accu = 0.0f;
            if (c > 0.0f) {
                prob = vp[i] / c;
                accu = va[i] / c;
                float gap = fabsf(prob - accu);
                if (gap > mce) mce = gap;
            }
            out[1 + i]          = prob;
            out[1 + N_BINS + i] = accu;
            vc[i] = 0.0f; vp[i] = 0.0f; va[i] = 0.0f;   // reset for next replay
        }
        out[0] = mce;
        g_done = 0u;
    }
}

extern "C" void kernel_launch(void* const* d_in, const int* in_sizes, int n_in,
                              void* d_out, int out_size) {
    const float4* logits4 = (const float4*)d_in[0];
    const float*  logits  = (const float*)d_in[0];
    const int*    labels  = (const int*)d_in[1];
    int nrows = in_sizes[1];               // labels element count == N rows

    // ~96 regs -> 2 CTAs/SM; exactly one wave of 296 blocks
    mce_main_kernel<<<296, 256>>>(logits4, logits, labels, (float*)d_out, nrows);
}

// round 9
// speedup vs baseline: 1.0878x; 1.0878x over previous
#include <cuda_runtime.h>
#include <math_constants.h>

#define N_BINS 15
#define RPW 8          // rows per warp per iter (2 rows per lane, 4 segments)

// Global scratch (no allocation allowed). Zeroed at module load; the fused
// finalizer re-zeroes after each use, so every graph replay starts from zero.
__device__ float    g_cnt[N_BINS];
__device__ float    g_conf[N_BINS];
__device__ float    g_acc[N_BINS];
__device__ unsigned g_done;

__device__ __forceinline__ float ex2f(float x) {
    float r;
    asm volatile("ex2.approx.f32 %0, %1;" : "=f"(r) : "f"(x));
    return r;
}

#define LOG2E 1.4426950408889634f

// Extract column `lab` (0..127) of the row held by this 8-lane segment.
// Lane sub owns float4 indices {sub, sub+8, sub+16, sub+24}; returns the
// value on the owning lane (garbage elsewhere) plus an ownership flag.
// Pure SEL chain — replaces the old dependent logits[row*128+lab] load.
__device__ __forceinline__ float extract_col(const float4 v[4], int lab, int sub,
                                             bool& owner)
{
    int f4  = lab >> 2;            // float4 index 0..31
    owner   = ((f4 & 7) == sub);   // owning lane within segment
    int i   = f4 >> 3;             // which of my 4 float4s
    int c   = lab & 3;             // component
    float4 f01 = (i & 1) ? v[1] : v[0];
    float4 f23 = (i & 1) ? v[3] : v[2];
    float4 f   = (i & 2) ? f23 : f01;
    float  lo  = (c & 1) ? f.y : f.x;
    float  hi  = (c & 1) ? f.w : f.z;
    return (c & 2) ? hi : lo;
}

// 8 lanes per row, 2 rows per lane: each LDG.128 covers 4 FULL 128B lines.
// A warp processes 8 consecutive rows per iteration (4 KB, front-batched).
// No atomics and no dependent loads in the hot loop.
__global__ void __launch_bounds__(256, 4) mce_main_kernel(
    const float4* __restrict__ logits4,   // [nrows * 32] float4
    const int*    __restrict__ labels,    // [nrows]
    float*        __restrict__ out,
    int nrows)
{
    __shared__ float s_cnt[N_BINS];
    __shared__ float s_conf[N_BINS];
    __shared__ float s_acc[N_BINS];
    __shared__ bool  s_last;

    int tid = threadIdx.x;
    if (tid < N_BINS) {
        s_cnt[tid]  = 0.0f;
        s_conf[tid] = 0.0f;
        s_acc[tid]  = 0.0f;
    }
    __syncthreads();

    int lane   = tid & 31;
    int seg    = lane >> 3;                // segment 0..3
    int sub    = lane & 7;                 // lane within 8-lane segment
    int warp   = (blockIdx.x * blockDim.x + tid) >> 5;
    int nwarps = (gridDim.x * blockDim.x) >> 5;

    float r_cnt = 0.0f, r_conf = 0.0f, r_acc = 0.0f;

    for (int base = warp * RPW; base < nrows; base += nwarps * RPW) {
        int rowA = base + seg;             // rows 0..3 of the group
        int rowB = base + seg + 4;         // rows 4..7 of the group
        int rowAc = (rowA < nrows) ? rowA : (nrows - 1);
        int rowBc = (rowB < nrows) ? rowB : (nrows - 1);

        // ---- independent front batch: 8 full-line LDG.128 + 2 label LDGs ----
        float4 vA[4], vB[4];
        const float4* rpA = logits4 + (size_t)rowAc * 32 + sub;
        const float4* rpB = logits4 + (size_t)rowBc * 32 + sub;
        #pragma unroll
        for (int i = 0; i < 4; i++) vA[i] = __ldcs(rpA + 8 * i);
        #pragma unroll
        for (int i = 0; i < 4; i++) vB[i] = __ldcs(rpB + 8 * i);
        int labA = labels[rowAc];
        int labB = labels[rowBc];

        // ---- per-lane max over 16 values each row ----
        float p0 = fmaxf(fmaxf(vA[0].x, vA[0].y), fmaxf(vA[0].z, vA[0].w));
        float p1 = fmaxf(fmaxf(vA[1].x, vA[1].y), fmaxf(vA[1].z, vA[1].w));
        float p2 = fmaxf(fmaxf(vA[2].x, vA[2].y), fmaxf(vA[2].z, vA[2].w));
        float p3 = fmaxf(fmaxf(vA[3].x, vA[3].y), fmaxf(vA[3].z, vA[3].w));
        float mA = fmaxf(fmaxf(p0, p1), fmaxf(p2, p3));
        float q0 = fmaxf(fmaxf(vB[0].x, vB[0].y), fmaxf(vB[0].z, vB[0].w));
        float q1 = fmaxf(fmaxf(vB[1].x, vB[1].y), fmaxf(vB[1].z, vB[1].w));
        float q2 = fmaxf(fmaxf(vB[2].x, vB[2].y), fmaxf(vB[2].z, vB[2].w));
        float q3 = fmaxf(fmaxf(vB[3].x, vB[3].y), fmaxf(vB[3].z, vB[3].w));
        float mB = fmaxf(fmaxf(q0, q1), fmaxf(q2, q3));

        // 3-level segment butterflies, two rows interleaved
        #pragma unroll
        for (int off = 1; off <= 4; off <<= 1) {
            mA = fmaxf(mA, __shfl_xor_sync(0xffffffffu, mA, off));
            mB = fmaxf(mB, __shfl_xor_sync(0xffffffffu, mB, off));
        }

        // ---- sum of exp(x - m) = ex2(x*log2e - m*log2e) ----
        float mLA = mA * LOG2E, mLB = mB * LOG2E;
        float sA = 0.0f, sB = 0.0f;
        #pragma unroll
        for (int i = 0; i < 4; i++) {
            float a0 = ex2f(fmaf(vA[i].x, LOG2E, -mLA));
            float a1 = ex2f(fmaf(vA[i].y, LOG2E, -mLA));
            float a2 = ex2f(fmaf(vA[i].z, LOG2E, -mLA));
            float a3 = ex2f(fmaf(vA[i].w, LOG2E, -mLA));
            sA += (a0 + a1) + (a2 + a3);
            float b0 = ex2f(fmaf(vB[i].x, LOG2E, -mLB));
            float b1 = ex2f(fmaf(vB[i].y, LOG2E, -mLB));
            float b2 = ex2f(fmaf(vB[i].z, LOG2E, -mLB));
            float b3 = ex2f(fmaf(vB[i].w, LOG2E, -mLB));
            sB += (b0 + b1) + (b2 + b3);
        }
        #pragma unroll
        for (int off = 1; off <= 4; off <<= 1) {
            sA += __shfl_xor_sync(0xffffffffu, sA, off);
            sB += __shfl_xor_sync(0xffffffffu, sB, off);
        }

        float confA = __fdividef(1.0f, sA);    // = exp(max)/sum exp
        float confB = __fdividef(1.0f, sB);

        // ---- accuracy: label column extracted from registers (no load) ----
        bool ownA, ownB;
        float lvA = extract_col(vA, labA, sub, ownA);
        float lvB = extract_col(vB, labB, sub, ownB);
        unsigned bA = __ballot_sync(0xffffffffu, ownA && (lvA == mA));
        unsigned bB = __ballot_sync(0xffffffffu, ownB && (lvB == mB));

        int nr = min(RPW, nrows - base);
        #pragma unroll
        for (int r = 0; r < RPW; r++) {
            float cf = (r < 4)
                     ? __shfl_sync(0xffffffffu, confA, (r & 3) * 8)
                     : __shfl_sync(0xffffffffu, confB, (r & 3) * 8);
            unsigned seg8 = (r & 3) * 8;
            unsigned abit = (r < 4) ? ((bA >> seg8) & 0xffu)
                                    : ((bB >> seg8) & 0xffu);
            // bin i covers (i/15, (i+1)/15]; conf >= 1/128 -> bin >= 0
            int bin = min(__float2int_ru(cf * (float)N_BINS) - 1, N_BINS - 1);
            if (bin == lane && r < nr) {
                r_cnt  += 1.0f;
                r_conf += cf;
                r_acc  += (abit != 0u) ? 1.0f : 0.0f;
            }
        }
    }

    // ---- flush: registers -> shared -> global (once per block) ----
    if (lane < N_BINS && r_cnt != 0.0f) {
        atomicAdd(&s_cnt[lane],  r_cnt);
        atomicAdd(&s_conf[lane], r_conf);
        atomicAdd(&s_acc[lane],  r_acc);
    }
    __syncthreads();
    if (tid < N_BINS) {
        float c = s_cnt[tid];
        if (c != 0.0f) {
            atomicAdd(&g_cnt[tid],  c);
            atomicAdd(&g_conf[tid], s_conf[tid]);
            atomicAdd(&g_acc[tid],  s_acc[tid]);
        }
    }
    __threadfence();
    __syncthreads();

    // ---- last block finalizes (fused; no second launch) ----
    if (tid == 0)
        s_last = (atomicAdd(&g_done, 1u) == gridDim.x - 1u);
    __syncthreads();
    if (s_last && tid == 0) {
        volatile float* vc = g_cnt;
        volatile float* vp = g_conf;
        volatile float* va = g_acc;
        float mce = -CUDART_INF_F;
        #pragma unroll
        for (int i = 0; i < N_BINS; i++) {
            float c    = vc[i];
            float prob = 0.0f, accu = 0.0f;
            if (c > 0.0f) {
                prob = vp[i] / c;
                accu = va[i] / c;
                float gap = fabsf(prob - accu);
                if (gap > mce) mce = gap;
            }
            out[1 + i]          = prob;
            out[1 + N_BINS + i] = accu;
            vc[i] = 0.0f; vp[i] = 0.0f; va[i] = 0.0f;   // reset for next replay
        }
        out[0] = mce;
        g_done = 0u;
    }
}

extern "C" void kernel_launch(void* const* d_in, const int* in_sizes, int n_in,
                              void* d_out, int out_size) {
    const float4* logits4 = (const float4*)d_in[0];
    const int*    labels  = (const int*)d_in[1];
    int nrows = in_sizes[1];               // labels element count == N rows

    // 4 CTAs/SM x 148 SMs = 592 blocks; grid-stride over row groups
    mce_main_kernel<<<592, 256>>>(logits4, labels, (float*)d_out, nrows);
}